// round 15
// baseline (speedup 1.0000x reference)
#include <cuda_runtime.h>
#include <math.h>

#define EPS 1e-6f
#define COLSB 128
#define ROWS 4
#define RBPP (COLSB / ROWS)  // row-blocks per full panel step

// Interval endpoints from sign predicates + snapped distances.
// valid_k == (di*dj<=0) & !(di==0 & dj==0) for snapped d (|d|>=EPS or 0).
// valid => di != dj, so the divide needs no guard.
__device__ __forceinline__ void interval3(const float p[3], const float d[3],
                                          const bool pp[3], const bool nn[3],
                                          float& tmin, float& tmax) {
    tmin = INFINITY;
    tmax = -INFINITY;
#pragma unroll
    for (int k = 0; k < 3; k++) {
        const int kn = (k == 2) ? 0 : k + 1;
        bool valid = !((pp[k] & pp[kn]) | (nn[k] & nn[kn])) &
                     (pp[k] | nn[k] | pp[kn] | nn[kn]);
        float t = p[k] + (p[kn] - p[k]) * __fdividef(d[k], d[k] - d[kn]);
        if (valid) {
            tmin = fminf(tmin, t);
            tmax = fmaxf(tmax, t);
        }
    }
}

__device__ __forceinline__ float sel3(int ax, float x, float y, float z) {
    return (ax == 0) ? x : ((ax == 1) ? y : z);
}

// Core pair test. Row triangle A arrives via 3x LDS.128 (padded 48B shared
// row, broadcast); the axis-projected coords pv re-read shared dynamically
// (<=3 distinct adjacent words per warp -> conflict-free, LSU pipe instead
// of FSELs on the saturated alu pipe). Snap via combined sign predicates:
//   pz = d>=EPS <=> snapped>0 ; nz = d<=-EPS <=> snapped<0 ;
//   snapped = (pz|nz) ? d : 0  (exactly the reference's snapped value).
__device__ __forceinline__ bool pair_test(const float* __restrict__ aRow,
                                          const float4 na,
                                          const float* __restrict__ B,
                                          const float4 nb) {
    const float4* a4 = (const float4*)aRow;
    float4 A0 = a4[0], A1 = a4[1];
    float A8 = a4[2].x;
    float A[9] = {A0.x, A0.y, A0.z, A0.w, A1.x, A1.y, A1.z, A1.w, A8};

    float dv[3], du[3];
    bool pv_[3], nv_[3], pu_[3], nu_[3];
#pragma unroll
    for (int v = 0; v < 3; v++) {
        float dd = A[3 * v] * nb.x + A[3 * v + 1] * nb.y +
                   A[3 * v + 2] * nb.z + nb.w;
        bool pz = dd >= EPS;
        bool nz = dd <= -EPS;
        dv[v] = (pz | nz) ? dd : 0.0f;
        pv_[v] = pz;
        nv_[v] = nz;
        float ee = B[3 * v] * na.x + B[3 * v + 1] * na.y +
                   B[3 * v + 2] * na.z + na.w;
        bool pz2 = ee >= EPS;
        bool nz2 = ee <= -EPS;
        du[v] = (pz2 | nz2) ? ee : 0.0f;
        pu_[v] = pz2;
        nu_[v] = nz2;
    }

    bool ssv = (pv_[0] & pv_[1] & pv_[2]) | (nv_[0] & nv_[1] & nv_[2]);
    bool ssu = (pu_[0] & pu_[1] & pu_[2]) | (nu_[0] & nu_[1] & nu_[2]);

    // Dominant axis of na x nb (first-max argmax).
    float Dx = na.y * nb.z - na.z * nb.y;
    float Dy = na.z * nb.x - na.x * nb.z;
    float Dz = na.x * nb.y - na.y * nb.x;
    int ax = 0;
    float m = fabsf(Dx);
    if (fabsf(Dy) > m) { ax = 1; m = fabsf(Dy); }
    if (fabsf(Dz) > m) { ax = 2; }

    float pv[3], pu[3];
#pragma unroll
    for (int v = 0; v < 3; v++) {
        pv[v] = aRow[3 * v + ax];  // dynamic LDS, <=3 distinct addrs per warp
        pu[v] = sel3(ax, B[3 * v], B[3 * v + 1], B[3 * v + 2]);
    }

    float t0v, t1v, t0u, t1u;
    interval3(pv, dv, pv_, nv_, t0v, t1v);
    interval3(pu, du, pu_, nu_, t0u, t1u);
    return !ssv & !ssu & (fmaxf(t0v, t0u) <= fminf(t1v, t1u));
}

// Cumulative row-block count before panel p (valid for full panels).
__device__ __forceinline__ int cum_rb(int p) { return RBPP * p * (p + 1) / 2; }

__global__ __launch_bounds__(COLSB, 9)
void pair_kernel(const float* __restrict__ T, float* __restrict__ out,
                 int N, int P) {
    // O(1) decode: linear tile id -> (panel p, row-block).
    const int k = blockIdx.x;
    int p = (int)((sqrtf(1.0f + (8.0f / RBPP) * (float)k) - 1.0f) * 0.5f);
    if (p > P - 1) p = P - 1;
    while (p + 1 <= P - 1 && cum_rb(p + 1) <= k) p++;
    while (p > 0 && cum_rb(p) > k) p--;
    const int c0 = p * COLSB;
    const int r0 = (k - cum_rb(p)) * ROWS;

    __shared__ float sA[ROWS][12];  // 48B rows (16B-aligned) for LDS.128
    __shared__ float4 sP[ROWS];

    const int tid = threadIdx.x;

    if (tid < ROWS * 12) {
        int r = tid / 12, c = tid % 12;
        int gi = r0 + r;
        sA[r][c] = (c < 9 && gi < N) ? T[(size_t)gi * 9 + c] : 0.0f;
    }
    __syncthreads();
    if (tid < ROWS) {
        const float* t = sA[tid];
        float e1x = t[3] - t[0], e1y = t[4] - t[1], e1z = t[5] - t[2];
        float e2x = t[6] - t[0], e2y = t[7] - t[1], e2z = t[8] - t[2];
        float nx = e1y * e2z - e1z * e2y;
        float ny = e1z * e2x - e1x * e2z;
        float nz = e1x * e2y - e1y * e2x;
        sP[tid] = make_float4(nx, ny, nz, -(nx * t[0] + ny * t[1] + nz * t[2]));
    }

    const int j = c0 + tid;
    const bool jok = j < N;
    const int jc = jok ? j : (N - 1);

    float B[9];
    const float* tb = T + (size_t)jc * 9;
#pragma unroll
    for (int c = 0; c < 9; c++) B[c] = __ldg(tb + c);
    float4 nb;
    {
        float e1x = B[3] - B[0], e1y = B[4] - B[1], e1z = B[5] - B[2];
        float e2x = B[6] - B[0], e2y = B[7] - B[1], e2z = B[8] - B[2];
        nb.x = e1y * e2z - e1z * e2y;
        nb.y = e1z * e2x - e1x * e2z;
        nb.z = e1x * e2y - e1y * e2x;
        nb.w = -(nb.x * B[0] + nb.y * B[1] + nb.z * B[2]);
    }
    __syncthreads();

    const bool interior = (r0 + ROWS <= c0) && (c0 + COLSB <= N);

    if (interior) {
        unsigned hitmask = 0;
#pragma unroll
        for (int r = 0; r < ROWS; r++) {
            bool hit = pair_test(sA[r], sP[r], B, nb);
            hitmask |= (hit ? 1u : 0u) << r;
            out[(size_t)(r0 + r) * N + j] = hit ? 1.0f : 0.0f;  // coalesced
        }
        float4 v0;
        v0.x = (hitmask & 1u) ? 1.0f : 0.0f;
        v0.y = (hitmask & 2u) ? 1.0f : 0.0f;
        v0.z = (hitmask & 4u) ? 1.0f : 0.0f;
        v0.w = (hitmask & 8u) ? 1.0f : 0.0f;
        *(float4*)(out + (size_t)j * N + r0) = v0;
    } else {
        unsigned hitmask = 0;
#pragma unroll
        for (int r = 0; r < ROWS; r++) {
            const int i = r0 + r;
            bool hit = pair_test(sA[r], sP[r], B, nb);
            hitmask |= (hit ? 1u : 0u) << r;
            float val = (i == j) ? 1.0f : (hit ? 1.0f : 0.0f);
            if (jok & (i <= j) & (i < N)) out[(size_t)i * N + j] = val;
        }
        if (jok) {
#pragma unroll
            for (int r = 0; r < ROWS; r++) {
                int i = r0 + r;
                if ((i < j) & (i < N))
                    out[(size_t)j * N + i] = (hitmask >> r & 1u) ? 1.0f : 0.0f;
            }
        }
    }
}

extern "C" void kernel_launch(void* const* d_in, const int* in_sizes, int n_in,
                              void* d_out, int out_size) {
    const float* T = (const float*)d_in[0];
    float* out = (float*)d_out;
    int N = in_sizes[0] / 9;

    int P = (N + COLSB - 1) / COLSB;
    int nblk = 0;
    for (int p = 0; p < P; p++) {
        int lim = (p + 1) * COLSB;
        if (lim > N) lim = N;
        nblk += (lim + ROWS - 1) / ROWS;
    }
    pair_kernel<<<nblk, COLSB>>>(T, out, N, P);
}

// round 16
// speedup vs baseline: 1.0102x; 1.0102x over previous
#include <cuda_runtime.h>
#include <math.h>

#define EPS 1e-6f
#define COLSB 128
#define ROWS 4
#define RBPP (COLSB / ROWS)  // row-blocks per full panel step

// Interval endpoints from sign predicates + snapped distances.
// valid_k == (di*dj<=0) & !(di==0 & dj==0) for snapped d (|d|>=EPS or 0).
// valid => di != dj, so the divide needs no guard.
__device__ __forceinline__ void interval3(const float p[3], const float d[3],
                                          const bool pp[3], const bool nn[3],
                                          float& tmin, float& tmax) {
    tmin = INFINITY;
    tmax = -INFINITY;
#pragma unroll
    for (int k = 0; k < 3; k++) {
        const int kn = (k == 2) ? 0 : k + 1;
        bool valid = !((pp[k] & pp[kn]) | (nn[k] & nn[kn])) &
                     (pp[k] | nn[k] | pp[kn] | nn[kn]);
        float t = p[k] + (p[kn] - p[k]) * __fdividef(d[k], d[k] - d[kn]);
        if (valid) {
            tmin = fminf(tmin, t);
            tmax = fmaxf(tmax, t);
        }
    }
}

__device__ __forceinline__ float sel3(int ax, float x, float y, float z) {
    return (ax == 0) ? x : ((ax == 1) ? y : z);
}

// Core pair test. Row triangle A arrives via 3x LDS.128 (padded 48B shared
// row, broadcast). Snap via combined sign predicates:
//   pz = d>=EPS <=> snapped>0 ; nz = d<=-EPS <=> snapped<0 ;
//   snapped = (pz|nz) ? d : 0  (exactly the reference's snapped value).
__device__ __forceinline__ bool pair_test(const float4* __restrict__ a4,
                                          const float4 na,
                                          const float* __restrict__ B,
                                          const float4 nb) {
    float4 A0 = a4[0], A1 = a4[1];
    float A8 = a4[2].x;
    float A[9] = {A0.x, A0.y, A0.z, A0.w, A1.x, A1.y, A1.z, A1.w, A8};

    float dv[3], du[3];
    bool pv_[3], nv_[3], pu_[3], nu_[3];
#pragma unroll
    for (int v = 0; v < 3; v++) {
        float dd = A[3 * v] * nb.x + A[3 * v + 1] * nb.y +
                   A[3 * v + 2] * nb.z + nb.w;
        bool pz = dd >= EPS;
        bool nz = dd <= -EPS;
        dv[v] = (pz | nz) ? dd : 0.0f;
        pv_[v] = pz;
        nv_[v] = nz;
        float ee = B[3 * v] * na.x + B[3 * v + 1] * na.y +
                   B[3 * v + 2] * na.z + na.w;
        bool pz2 = ee >= EPS;
        bool nz2 = ee <= -EPS;
        du[v] = (pz2 | nz2) ? ee : 0.0f;
        pu_[v] = pz2;
        nu_[v] = nz2;
    }

    bool ssv = (pv_[0] & pv_[1] & pv_[2]) | (nv_[0] & nv_[1] & nv_[2]);
    bool ssu = (pu_[0] & pu_[1] & pu_[2]) | (nu_[0] & nu_[1] & nu_[2]);

    // Dominant axis of na x nb (first-max argmax).
    float Dx = na.y * nb.z - na.z * nb.y;
    float Dy = na.z * nb.x - na.x * nb.z;
    float Dz = na.x * nb.y - na.y * nb.x;
    int ax = 0;
    float m = fabsf(Dx);
    if (fabsf(Dy) > m) { ax = 1; m = fabsf(Dy); }
    if (fabsf(Dz) > m) { ax = 2; }

    float pv[3], pu[3];
#pragma unroll
    for (int v = 0; v < 3; v++) {
        pv[v] = sel3(ax, A[3 * v], A[3 * v + 1], A[3 * v + 2]);
        pu[v] = sel3(ax, B[3 * v], B[3 * v + 1], B[3 * v + 2]);
    }

    float t0v, t1v, t0u, t1u;
    interval3(pv, dv, pv_, nv_, t0v, t1v);
    interval3(pu, du, pu_, nu_, t0u, t1u);
    return !ssv & !ssu & (fmaxf(t0v, t0u) <= fminf(t1v, t1u));
}

// Cumulative row-block count before panel p (valid for full panels).
__device__ __forceinline__ int cum_rb(int p) { return RBPP * p * (p + 1) / 2; }

__global__ __launch_bounds__(COLSB, 10)
void pair_kernel(const float* __restrict__ T, float* __restrict__ out,
                 int N, int P) {
    // O(1) decode: linear tile id -> (panel p, row-block).
    const int k = blockIdx.x;
    int p = (int)((sqrtf(1.0f + (8.0f / RBPP) * (float)k) - 1.0f) * 0.5f);
    if (p > P - 1) p = P - 1;
    while (p + 1 <= P - 1 && cum_rb(p + 1) <= k) p++;
    while (p > 0 && cum_rb(p) > k) p--;
    const int c0 = p * COLSB;
    const int r0 = (k - cum_rb(p)) * ROWS;

    __shared__ float sA[ROWS][12];  // 48B rows (16B-aligned) for LDS.128
    __shared__ float4 sP[ROWS];

    const int tid = threadIdx.x;

    if (tid < ROWS * 12) {
        int r = tid / 12, c = tid % 12;
        int gi = r0 + r;
        sA[r][c] = (c < 9 && gi < N) ? T[(size_t)gi * 9 + c] : 0.0f;
    }
    __syncthreads();
    if (tid < ROWS) {
        const float* t = sA[tid];
        float e1x = t[3] - t[0], e1y = t[4] - t[1], e1z = t[5] - t[2];
        float e2x = t[6] - t[0], e2y = t[7] - t[1], e2z = t[8] - t[2];
        float nx = e1y * e2z - e1z * e2y;
        float ny = e1z * e2x - e1x * e2z;
        float nz = e1x * e2y - e1y * e2x;
        sP[tid] = make_float4(nx, ny, nz, -(nx * t[0] + ny * t[1] + nz * t[2]));
    }

    const int j = c0 + tid;
    const bool jok = j < N;
    const int jc = jok ? j : (N - 1);

    float B[9];
    const float* tb = T + (size_t)jc * 9;
#pragma unroll
    for (int c = 0; c < 9; c++) B[c] = __ldg(tb + c);
    float4 nb;
    {
        float e1x = B[3] - B[0], e1y = B[4] - B[1], e1z = B[5] - B[2];
        float e2x = B[6] - B[0], e2y = B[7] - B[1], e2z = B[8] - B[2];
        nb.x = e1y * e2z - e1z * e2y;
        nb.y = e1z * e2x - e1x * e2z;
        nb.z = e1x * e2y - e1y * e2x;
        nb.w = -(nb.x * B[0] + nb.y * B[1] + nb.z * B[2]);
    }
    __syncthreads();

    const bool interior = (r0 + ROWS <= c0) && (c0 + COLSB <= N);

    if (interior) {
        unsigned hitmask = 0;
#pragma unroll
        for (int r = 0; r < ROWS; r++) {
            bool hit = pair_test((const float4*)sA[r], sP[r], B, nb);
            hitmask |= (hit ? 1u : 0u) << r;
            out[(size_t)(r0 + r) * N + j] = hit ? 1.0f : 0.0f;  // coalesced
        }
        float4 v0;
        v0.x = (hitmask & 1u) ? 1.0f : 0.0f;
        v0.y = (hitmask & 2u) ? 1.0f : 0.0f;
        v0.z = (hitmask & 4u) ? 1.0f : 0.0f;
        v0.w = (hitmask & 8u) ? 1.0f : 0.0f;
        *(float4*)(out + (size_t)j * N + r0) = v0;
    } else {
        unsigned hitmask = 0;
#pragma unroll
        for (int r = 0; r < ROWS; r++) {
            const int i = r0 + r;
            bool hit = pair_test((const float4*)sA[r], sP[r], B, nb);
            hitmask |= (hit ? 1u : 0u) << r;
            float val = (i == j) ? 1.0f : (hit ? 1.0f : 0.0f);
            if (jok & (i <= j) & (i < N)) out[(size_t)i * N + j] = val;
        }
        if (jok) {
#pragma unroll
            for (int r = 0; r < ROWS; r++) {
                int i = r0 + r;
                if ((i < j) & (i < N))
                    out[(size_t)j * N + i] = (hitmask >> r & 1u) ? 1.0f : 0.0f;
            }
        }
    }
}

extern "C" void kernel_launch(void* const* d_in, const int* in_sizes, int n_in,
                              void* d_out, int out_size) {
    const float* T = (const float*)d_in[0];
    float* out = (float*)d_out;
    int N = in_sizes[0] / 9;

    int P = (N + COLSB - 1) / COLSB;
    int nblk = 0;
    for (int p = 0; p < P; p++) {
        int lim = (p + 1) * COLSB;
        if (lim > N) lim = N;
        nblk += (lim + ROWS - 1) / ROWS;
    }
    pair_kernel<<<nblk, COLSB>>>(T, out, N, P);
}